// round 3
// baseline (speedup 1.0000x reference)
#include <cuda_runtime.h>
#include <cstdint>

// SupportLowRankRNN: B=32, T=1000, H=2048, I=4, R=2, O=2, S=2, G=8
#define TT       1000
#define HID      2048
#define NTHREADS 512
#define NWARPS   16
#define ALPHA_F  0.2f
#define OMA_F    0.8f      // 1 - ALPHA
#define SIG_F    0.05f     // NOISE_STD
#define L2E2X    2.8853900817779268f  // 2*log2(e)

// smem layout (floats)
#define SM_NOISE 0                       // 4 stages * 2048
#define SM_IN    (4*HID)                 // 4000  (input seq, 1000*4)
#define SM_RED   (SM_IN + 4000)          // 2*16*4 = 128 (parity-double-buffered partials)
#define SM_W     (SM_RED + 128)          // 192 staged weights
#define SM_FLOATS (SM_W + 192)
#define SMEM_BYTES (SM_FLOATS * 4)       // 50048

// weight staging offsets inside SM_W
#define W_WI  0     // 64  (4,2,8)
#define W_M   64    // 32  (2,2,8)
#define W_N   96    // 32
#define W_WO  128   // 32
#define W_WIB 160   // 8   (4,2)
#define W_MB  168   // 4
#define W_NB  172   // 4
#define W_H0  176   // 16  (2,8)

__device__ __forceinline__ unsigned long long f2u(float2 v){ union{float2 f; unsigned long long u;} x; x.f=v; return x.u; }
__device__ __forceinline__ float2 u2f(unsigned long long u){ union{float2 f; unsigned long long u;} x; x.u=u; return x.f; }
__device__ __forceinline__ float2 ffma2(float2 a,float2 b,float2 c){
  unsigned long long D; asm("fma.rn.f32x2 %0,%1,%2,%3;":"=l"(D):"l"(f2u(a)),"l"(f2u(b)),"l"(f2u(c))); return u2f(D);
}
__device__ __forceinline__ float2 fmul2(float2 a,float2 b){
  unsigned long long D; asm("mul.rn.f32x2 %0,%1,%2;":"=l"(D):"l"(f2u(a)),"l"(f2u(b))); return u2f(D);
}
__device__ __forceinline__ float2 fadd2(float2 a,float2 b){
  unsigned long long D; asm("add.rn.f32x2 %0,%1,%2;":"=l"(D):"l"(f2u(a)),"l"(f2u(b))); return u2f(D);
}
__device__ __forceinline__ float ex2a(float x){ float y; asm("ex2.approx.f32 %0,%1;":"=f"(y):"f"(x)); return y; }
__device__ __forceinline__ float rcpa(float x){ float y; asm("rcp.approx.f32 %0,%1;":"=f"(y):"f"(x)); return y; }
__device__ __forceinline__ void cp16(uint32_t s, const void* g){
  asm volatile("cp.async.ca.shared.global [%0], [%1], 16;"::"r"(s),"l"(g));
}
#define CP_COMMIT() asm volatile("cp.async.commit_group;")
#define CP_WAIT3()  asm volatile("cp.async.wait_group 3;")

// full-warp butterfly sum (32 lanes), 4 independent values reduced together
// so the SHFL latencies pipeline.
__device__ __forceinline__ void warp_sum4(float& a, float& b, float& c, float& d){
  #pragma unroll
  for (int o = 16; o > 0; o >>= 1) {
    a += __shfl_xor_sync(0xffffffffu, a, o);
    b += __shfl_xor_sync(0xffffffffu, b, o);
    c += __shfl_xor_sync(0xffffffffu, c, o);
    d += __shfl_xor_sync(0xffffffffu, d, o);
  }
}
// 16-lane butterfly (values valid in lanes 0..15, zero elsewhere)
__device__ __forceinline__ void warp_sum4_16(float& a, float& b, float& c, float& d){
  #pragma unroll
  for (int o = 8; o > 0; o >>= 1) {
    a += __shfl_xor_sync(0xffffffffu, a, o);
    b += __shfl_xor_sync(0xffffffffu, b, o);
    c += __shfl_xor_sync(0xffffffffu, c, o);
    d += __shfl_xor_sync(0xffffffffu, d, o);
  }
}

// accurate tanh: 1 - 2/(1 + e^{2x})  (ex2.approx + rcp.approx, ~1e-6 abs err)
__device__ __forceinline__ float2 tanh2(float2 h){
  float2 ea = fmul2(h, make_float2(L2E2X, L2E2X));
  float a0 = fminf(fmaxf(ea.x, -80.f), 80.f);
  float a1 = fminf(fmaxf(ea.y, -80.f), 80.f);
  float2 dd = fadd2(make_float2(ex2a(a0), ex2a(a1)), make_float2(1.f, 1.f));
  float2 rc = make_float2(rcpa(dd.x), rcpa(dd.y));
  return ffma2(make_float2(-2.f, -2.f), rc, make_float2(1.f, 1.f));
}

__global__ void __launch_bounds__(NTHREADS, 1)
rnn_main(const float* __restrict__ input,   // (32,1000,4)
         const float* __restrict__ noise,   // (32,1000,2048)
         const float* __restrict__ wi_w,    // (4,2,8)
         const float* __restrict__ m_w,     // (2,2,8)
         const float* __restrict__ n_w,     // (2,2,8)
         const float* __restrict__ wo_w,    // (2,2,8)
         const float* __restrict__ wi_b,    // (4,2)
         const float* __restrict__ m_b,     // (2,2)
         const float* __restrict__ n_b,     // (2,2)
         const float* __restrict__ h0_w,    // (2,8)
         const float* __restrict__ basis,   // (8,2048)
         const float* __restrict__ sup,     // (2,2048)
         float* __restrict__ out)           // (32,1000,2)
{
  const int b    = blockIdx.x;
  const int tid  = threadIdx.x;
  const int lane = tid & 31;
  const int warp = tid >> 5;
  const int u0   = tid * 4;   // 4 contiguous hidden units per thread

  extern __shared__ __align__(16) float sm[];
  float* s_noise = sm + SM_NOISE;
  float* s_in    = sm + SM_IN;
  float4* s_red4 = reinterpret_cast<float4*>(sm + SM_RED);
  float* s_w     = sm + SM_W;

  // ---- stage tiny weights to smem ----
  if (tid < 64)        s_w[tid] = wi_w[tid];
  else if (tid < 96)   s_w[tid] = m_w[tid - 64];
  else if (tid < 128)  s_w[tid] = n_w[tid - 96];
  else if (tid < 160)  s_w[tid] = wo_w[tid - 128];
  else if (tid < 168)  s_w[tid] = wi_b[tid - 160];
  else if (tid < 172)  s_w[tid] = m_b[tid - 168];
  else if (tid < 176)  s_w[tid] = n_b[tid - 172];
  else if (tid < 192)  s_w[tid] = h0_w[tid - 176];

  // ---- preload full input sequence (16KB) ----
  const float4* inb = reinterpret_cast<const float4*>(input + (size_t)b * (TT * 4));
  for (int i = tid; i < TT; i += NTHREADS)
    reinterpret_cast<float4*>(s_in)[i] = inb[i];

  // ---- noise cp.async pipeline prologue (stages 0..2) ----
  const float* nbase = noise + (size_t)b * TT * HID + u0;
  uint32_t sn_u32 = (uint32_t)__cvta_generic_to_shared(s_noise + u0);
  #pragma unroll
  for (int ps = 0; ps < 3; ps++) {
    cp16(sn_u32 + (uint32_t)ps * HID * 4, nbase + (size_t)ps * HID);
    CP_COMMIT();
  }

  __syncthreads();  // s_w + s_in ready

  // ---- compute this thread's per-unit params from basis/supports ----
  // packed as float2 pairs: pair p covers units (2p, 2p+1)
  float2 wip[4][2], n0p[2], n1p[2], ma0p[2], ma1p[2], wo0p[2], wo1p[2], hh[2];
  {
    float wia[4][4], nn0[4], nn1[4], mm0[4], mm1[4], ww0[4], ww1[4], h0v[4];
    #pragma unroll
    for (int j = 0; j < 4; j++) {
      const int h = u0 + j;
      float B[8];
      #pragma unroll
      for (int g = 0; g < 8; g++) B[g] = basis[g * HID + h];
      const float su0 = sup[h], su1 = sup[HID + h];
      #pragma unroll
      for (int x = 0; x < 4; x++) {
        float t0 = s_w[W_WIB + x*2 + 0], t1 = s_w[W_WIB + x*2 + 1];
        #pragma unroll
        for (int g = 0; g < 8; g++) { t0 += s_w[W_WI + x*16 + g]*B[g]; t1 += s_w[W_WI + x*16 + 8 + g]*B[g]; }
        wia[x][j] = ALPHA_F * (t0*su0 + t1*su1);
      }
      #pragma unroll
      for (int r = 0; r < 2; r++) {
        float tm0 = s_w[W_MB + r*2 + 0], tm1 = s_w[W_MB + r*2 + 1];
        float tn0 = s_w[W_NB + r*2 + 0], tn1 = s_w[W_NB + r*2 + 1];
        #pragma unroll
        for (int g = 0; g < 8; g++) {
          tm0 += s_w[W_M + r*16 + g]*B[g];     tm1 += s_w[W_M + r*16 + 8 + g]*B[g];
          tn0 += s_w[W_N + r*16 + g]*B[g];     tn1 += s_w[W_N + r*16 + 8 + g]*B[g];
        }
        float mv = ALPHA_F * (tm0*su0 + tm1*su1);
        float nv = tn0*su0 + tn1*su1;
        if (r == 0) { mm0[j] = mv; nn0[j] = nv; } else { mm1[j] = mv; nn1[j] = nv; }
      }
      #pragma unroll
      for (int o = 0; o < 2; o++) {
        float t0 = 0.f, t1 = 0.f;
        #pragma unroll
        for (int g = 0; g < 8; g++) { t0 += s_w[W_WO + o*16 + g]*B[g]; t1 += s_w[W_WO + o*16 + 8 + g]*B[g]; }
        float wv = t0*su0 + t1*su1;
        if (o == 0) ww0[j] = wv; else ww1[j] = wv;
      }
      {
        float t0 = 0.f, t1 = 0.f;
        #pragma unroll
        for (int g = 0; g < 8; g++) { t0 += s_w[W_H0 + g]*B[g]; t1 += s_w[W_H0 + 8 + g]*B[g]; }
        h0v[j] = t0*su0 + t1*su1;
      }
    }
    #pragma unroll
    for (int p = 0; p < 2; p++) {
      wip[0][p] = make_float2(wia[0][2*p], wia[0][2*p+1]);
      wip[1][p] = make_float2(wia[1][2*p], wia[1][2*p+1]);
      wip[2][p] = make_float2(wia[2][2*p], wia[2][2*p+1]);
      wip[3][p] = make_float2(wia[3][2*p], wia[3][2*p+1]);
      n0p[p]  = make_float2(nn0[2*p], nn0[2*p+1]);
      n1p[p]  = make_float2(nn1[2*p], nn1[2*p+1]);
      ma0p[p] = make_float2(mm0[2*p], mm0[2*p+1]);
      ma1p[p] = make_float2(mm1[2*p], mm1[2*p+1]);
      wo0p[p] = make_float2(ww0[2*p], ww0[2*p+1]);
      wo1p[p] = make_float2(ww1[2*p], ww1[2*p+1]);
      hh[p]   = make_float2(h0v[2*p], h0v[2*p+1]);
    }
  }

  // ---- initial r and partial dot products ----
  float pz0, pz1, po0, po1;
  {
    float2 az0 = make_float2(0,0), az1 = az0, ao0 = az0, ao1 = az0;
    #pragma unroll
    for (int p = 0; p < 2; p++) {
      float2 r2 = tanh2(hh[p]);
      az0 = ffma2(r2, n0p[p], az0);
      az1 = ffma2(r2, n1p[p], az1);
      ao0 = ffma2(r2, wo0p[p], ao0);
      ao1 = ffma2(r2, wo1p[p], ao1);
    }
    pz0 = az0.x + az0.y; pz1 = az1.x + az1.y;
    po0 = ao0.x + ao0.y; po1 = ao1.x + ao1.y;
  }

  const float2 OMA2 = make_float2(OMA_F, OMA_F);
  const float2 SIG2 = make_float2(SIG_F, SIG_F);

  // ---- main scan ----
  for (int t = 0; t < TT; t++) {
    const int pb = t & 1;
    // stage-1: warp butterfly of [z0, z1, o_prev0, o_prev1]
    warp_sum4(pz0, pz1, po0, po1);
    if (lane == 0) s_red4[pb * NWARPS + warp] = make_float4(pz0, pz1, po0, po1);

    // prefetch noise for t+3
    int tp = t + 3; if (tp >= TT) tp = TT - 1;
    cp16(sn_u32 + (uint32_t)(((t + 3) & 3) * HID * 4), nbase + (size_t)tp * HID);
    CP_COMMIT();

    __syncthreads();

    // stage-2: combine 16 warp partials (replicated per warp, no 2nd barrier)
    float4 w = make_float4(0.f, 0.f, 0.f, 0.f);
    if (lane < NWARPS) w = s_red4[pb * NWARPS + lane];
    float z0 = w.x, z1 = w.y, o0 = w.z, o1 = w.w;
    warp_sum4_16(z0, z1, o0, o1);
    // broadcast from lane 0 so all lanes agree (lanes 16..31 had zeros)
    z0 = __shfl_sync(0xffffffffu, z0, 0);
    z1 = __shfl_sync(0xffffffffu, z1, 0);
    o0 = __shfl_sync(0xffffffffu, o0, 0);
    o1 = __shfl_sync(0xffffffffu, o1, 0);

    if (tid == 0 && t > 0)
      reinterpret_cast<float2*>(out)[(size_t)b * TT + (t - 1)] = make_float2(o0, o1);

    CP_WAIT3();
    float4 g  = *reinterpret_cast<const float4*>(s_noise + (t & 3) * HID + u0);
    float4 xv = reinterpret_cast<const float4*>(s_in)[t];

    const float2 z0_2 = make_float2(z0, z0), z1_2 = make_float2(z1, z1);
    const float2 x0_2 = make_float2(xv.x, xv.x), x1_2 = make_float2(xv.y, xv.y);
    const float2 x2_2 = make_float2(xv.z, xv.z), x3_2 = make_float2(xv.w, xv.w);
    float2 gg[2] = { make_float2(g.x, g.y), make_float2(g.z, g.w) };

    float2 az0 = make_float2(0,0), az1 = az0, ao0 = az0, ao1 = az0;
    #pragma unroll
    for (int p = 0; p < 2; p++) {
      // h = 0.8h + 0.05*noise + alpha*(m z) + alpha*(wi x)   [alpha pre-folded]
      float2 acc = fmul2(z0_2, ma0p[p]);
      acc = ffma2(z1_2, ma1p[p], acc);
      acc = ffma2(OMA2, hh[p], acc);
      acc = ffma2(SIG2, gg[p], acc);
      acc = ffma2(x0_2, wip[0][p], acc);
      acc = ffma2(x1_2, wip[1][p], acc);
      acc = ffma2(x2_2, wip[2][p], acc);
      acc = ffma2(x3_2, wip[3][p], acc);
      hh[p] = acc;
      float2 r2 = tanh2(acc);
      az0 = ffma2(r2, n0p[p], az0);
      az1 = ffma2(r2, n1p[p], az1);
      ao0 = ffma2(r2, wo0p[p], ao0);
      ao1 = ffma2(r2, wo1p[p], ao1);
    }
    pz0 = az0.x + az0.y; pz1 = az1.x + az1.y;
    po0 = ao0.x + ao0.y; po1 = ao1.x + ao1.y;
  }

  // ---- final output (o of r_{T-1}) ----
  {
    const int pb = TT & 1;
    float d0 = 0.f, d1 = 0.f;
    warp_sum4(po0, po1, d0, d1);
    if (lane == 0) s_red4[pb * NWARPS + warp] = make_float4(0.f, 0.f, po0, po1);
    __syncthreads();
    float4 w = make_float4(0.f, 0.f, 0.f, 0.f);
    if (lane < NWARPS) w = s_red4[pb * NWARPS + lane];
    float o0 = w.z, o1 = w.w, e0 = 0.f, e1 = 0.f;
    warp_sum4_16(o0, o1, e0, e1);
    if (tid == 0)
      reinterpret_cast<float2*>(out)[(size_t)b * TT + (TT - 1)] = make_float2(o0, o1);
  }
}

extern "C" void kernel_launch(void* const* d_in, const int* in_sizes, int n_in,
                              void* d_out, int out_size) {
  const float* input = (const float*)d_in[0];
  const float* noise = (const float*)d_in[1];
  const float* wi_w  = (const float*)d_in[2];
  const float* m_w   = (const float*)d_in[3];
  const float* n_w   = (const float*)d_in[4];
  const float* wo_w  = (const float*)d_in[5];
  const float* wi_b  = (const float*)d_in[6];
  const float* m_b   = (const float*)d_in[7];
  const float* n_b   = (const float*)d_in[8];
  const float* h0_w  = (const float*)d_in[9];
  const float* basis = (const float*)d_in[10];
  const float* sup   = (const float*)d_in[11];
  float* out = (float*)d_out;

  cudaFuncSetAttribute(rnn_main, cudaFuncAttributeMaxDynamicSharedMemorySize, SMEM_BYTES);
  rnn_main<<<32, NTHREADS, SMEM_BYTES>>>(input, noise, wi_w, m_w, n_w, wo_w,
                                         wi_b, m_b, n_b, h0_w, basis, sup, out);
}

// round 4
// speedup vs baseline: 1.0284x; 1.0284x over previous
#include <cuda_runtime.h>
#include <cstdint>

// SupportLowRankRNN: B=32, T=1000, H=2048, I=4, R=2, O=2, S=2, G=8
#define TT       1000
#define HID      2048
#define NTHREADS 256
#define NWARPS   8
#define UNITS    8          // hidden units per thread
#define PAIRS    4          // float2 pairs per thread
#define ALPHA_F  0.2f
#define OMA_F    0.8f       // 1 - ALPHA
#define SIG_F    0.05f      // NOISE_STD
#define L2E2X    2.8853900817779268f  // 2*log2(e)

// smem layout (floats)
#define SM_NOISE 0                       // 4 stages * 2048
#define SM_IN    (4*HID)                 // 4000  (input seq, 1000*4)
#define SM_RED   (SM_IN + 4000)          // 2*16 (parity-double-buffered z partials, value-major)
#define SM_W     (SM_RED + 32)           // 192 staged weights
#define SM_FLOATS (SM_W + 192)
#define SMEM_BYTES (SM_FLOATS * 4)

// weight staging offsets inside SM_W
#define W_WI  0     // 64  (4,2,8)
#define W_M   64    // 32  (2,2,8)
#define W_N   96    // 32
#define W_WO  128   // 32
#define W_WIB 160   // 8   (4,2)
#define W_MB  168   // 4
#define W_NB  172   // 4
#define W_H0  176   // 16  (2,8)

// per-warp output partials: [b][t][warp][2]
__device__ float g_scratch[32 * TT * NWARPS * 2];

__device__ __forceinline__ unsigned long long f2u(float2 v){ union{float2 f; unsigned long long u;} x; x.f=v; return x.u; }
__device__ __forceinline__ float2 u2f(unsigned long long u){ union{float2 f; unsigned long long u;} x; x.u=u; return x.f; }
__device__ __forceinline__ float2 ffma2(float2 a,float2 b,float2 c){
  unsigned long long D; asm("fma.rn.f32x2 %0,%1,%2,%3;":"=l"(D):"l"(f2u(a)),"l"(f2u(b)),"l"(f2u(c))); return u2f(D);
}
__device__ __forceinline__ float2 fmul2(float2 a,float2 b){
  unsigned long long D; asm("mul.rn.f32x2 %0,%1,%2;":"=l"(D):"l"(f2u(a)),"l"(f2u(b))); return u2f(D);
}
__device__ __forceinline__ float2 fadd2(float2 a,float2 b){
  unsigned long long D; asm("add.rn.f32x2 %0,%1,%2;":"=l"(D):"l"(f2u(a)),"l"(f2u(b))); return u2f(D);
}
__device__ __forceinline__ float ex2a(float x){ float y; asm("ex2.approx.f32 %0,%1;":"=f"(y):"f"(x)); return y; }
__device__ __forceinline__ float rcpa(float x){ float y; asm("rcp.approx.f32 %0,%1;":"=f"(y):"f"(x)); return y; }
__device__ __forceinline__ void cp16(uint32_t s, const void* g){
  asm volatile("cp.async.ca.shared.global [%0], [%1], 16;"::"r"(s),"l"(g));
}
#define CP_COMMIT() asm volatile("cp.async.commit_group;")
#define CP_WAIT3()  asm volatile("cp.async.wait_group 3;")

// full-warp butterfly sum of 4 independent values (latencies pipeline)
__device__ __forceinline__ void warp_sum4(float& a, float& b, float& c, float& d){
  #pragma unroll
  for (int o = 16; o > 0; o >>= 1) {
    a += __shfl_xor_sync(0xffffffffu, a, o);
    b += __shfl_xor_sync(0xffffffffu, b, o);
    c += __shfl_xor_sync(0xffffffffu, c, o);
    d += __shfl_xor_sync(0xffffffffu, d, o);
  }
}

// tanh of a pair with ONE rcp (batched reciprocal): 1/d0 = inv*d1, 1/d1 = inv*d0.
// clamp exponent arg to +-60 so d0*d1 <= 2^121 never overflows; saturation exact.
__device__ __forceinline__ float2 tanh2m(float2 h){
  float2 ea = fmul2(h, make_float2(L2E2X, L2E2X));
  float a0 = fminf(fmaxf(ea.x, -60.f), 60.f);
  float a1 = fminf(fmaxf(ea.y, -60.f), 60.f);
  float2 d = fadd2(make_float2(ex2a(a0), ex2a(a1)), make_float2(1.f, 1.f));
  float inv = rcpa(d.x * d.y);
  float s = -2.f * inv;
  return make_float2(fmaf(s, d.y, 1.f), fmaf(s, d.x, 1.f));
}

__global__ void __launch_bounds__(NTHREADS, 1)
rnn_main(const float* __restrict__ input,   // (32,1000,4)
         const float* __restrict__ noise,   // (32,1000,2048)
         const float* __restrict__ wi_w, const float* __restrict__ m_w,
         const float* __restrict__ n_w, const float* __restrict__ wo_w,
         const float* __restrict__ wi_b, const float* __restrict__ m_b,
         const float* __restrict__ n_b, const float* __restrict__ h0_w,
         const float* __restrict__ basis,   // (8,2048)
         const float* __restrict__ sup)     // (2,2048)
{
  const int b    = blockIdx.x;
  const int tid  = threadIdx.x;
  const int lane = tid & 31;
  const int warp = tid >> 5;
  const int u0   = tid * UNITS;   // 8 contiguous hidden units per thread

  extern __shared__ __align__(16) float sm[];
  float* s_noise = sm + SM_NOISE;
  float* s_in    = sm + SM_IN;
  float* s_red   = sm + SM_RED;
  float* s_w     = sm + SM_W;

  // ---- stage tiny weights to smem ----
  if (tid < 64)        s_w[tid] = wi_w[tid];
  else if (tid < 96)   s_w[tid] = m_w[tid - 64];
  else if (tid < 128)  s_w[tid] = n_w[tid - 96];
  else if (tid < 160)  s_w[tid] = wo_w[tid - 128];
  else if (tid < 168)  s_w[tid] = wi_b[tid - 160];
  else if (tid < 172)  s_w[tid] = m_b[tid - 168];
  else if (tid < 176)  s_w[tid] = n_b[tid - 172];
  else if (tid < 192)  s_w[tid] = h0_w[tid - 176];

  // ---- preload full input sequence (16KB) ----
  const float4* inb = reinterpret_cast<const float4*>(input + (size_t)b * (TT * 4));
  for (int i = tid; i < TT; i += NTHREADS)
    reinterpret_cast<float4*>(s_in)[i] = inb[i];

  // ---- noise cp.async pipeline prologue (stages 0..2), 32B/thread/stage ----
  const float* nbase = noise + (size_t)b * TT * HID + u0;
  uint32_t sn_u32 = (uint32_t)__cvta_generic_to_shared(s_noise + u0);
  #pragma unroll
  for (int ps = 0; ps < 3; ps++) {
    cp16(sn_u32 + (uint32_t)ps * HID * 4,      nbase + (size_t)ps * HID);
    cp16(sn_u32 + (uint32_t)ps * HID * 4 + 16, nbase + (size_t)ps * HID + 4);
    CP_COMMIT();
  }

  __syncthreads();  // s_w + s_in ready

  // ---- per-unit params from basis/supports; packed float2 pairs ----
  float2 wip[4][PAIRS], n0p[PAIRS], n1p[PAIRS], ma0p[PAIRS], ma1p[PAIRS],
         wo0p[PAIRS], wo1p[PAIRS], hh[PAIRS];
  {
    float wia[4][UNITS], nn0[UNITS], nn1[UNITS], mm0[UNITS], mm1[UNITS],
          ww0[UNITS], ww1[UNITS], h0v[UNITS];
    #pragma unroll
    for (int j = 0; j < UNITS; j++) {
      const int h = u0 + j;
      float B[8];
      #pragma unroll
      for (int g = 0; g < 8; g++) B[g] = basis[g * HID + h];
      const float su0 = sup[h], su1 = sup[HID + h];
      #pragma unroll
      for (int x = 0; x < 4; x++) {
        float t0 = s_w[W_WIB + x*2 + 0], t1 = s_w[W_WIB + x*2 + 1];
        #pragma unroll
        for (int g = 0; g < 8; g++) { t0 += s_w[W_WI + x*16 + g]*B[g]; t1 += s_w[W_WI + x*16 + 8 + g]*B[g]; }
        wia[x][j] = ALPHA_F * (t0*su0 + t1*su1);
      }
      #pragma unroll
      for (int r = 0; r < 2; r++) {
        float tm0 = s_w[W_MB + r*2 + 0], tm1 = s_w[W_MB + r*2 + 1];
        float tn0 = s_w[W_NB + r*2 + 0], tn1 = s_w[W_NB + r*2 + 1];
        #pragma unroll
        for (int g = 0; g < 8; g++) {
          tm0 += s_w[W_M + r*16 + g]*B[g];  tm1 += s_w[W_M + r*16 + 8 + g]*B[g];
          tn0 += s_w[W_N + r*16 + g]*B[g];  tn1 += s_w[W_N + r*16 + 8 + g]*B[g];
        }
        float mv = ALPHA_F * (tm0*su0 + tm1*su1);
        float nv = tn0*su0 + tn1*su1;
        if (r == 0) { mm0[j] = mv; nn0[j] = nv; } else { mm1[j] = mv; nn1[j] = nv; }
      }
      #pragma unroll
      for (int o = 0; o < 2; o++) {
        float t0 = 0.f, t1 = 0.f;
        #pragma unroll
        for (int g = 0; g < 8; g++) { t0 += s_w[W_WO + o*16 + g]*B[g]; t1 += s_w[W_WO + o*16 + 8 + g]*B[g]; }
        float wv = t0*su0 + t1*su1;
        if (o == 0) ww0[j] = wv; else ww1[j] = wv;
      }
      {
        float t0 = 0.f, t1 = 0.f;
        #pragma unroll
        for (int g = 0; g < 8; g++) { t0 += s_w[W_H0 + g]*B[g]; t1 += s_w[W_H0 + 8 + g]*B[g]; }
        h0v[j] = t0*su0 + t1*su1;
      }
    }
    #pragma unroll
    for (int p = 0; p < PAIRS; p++) {
      wip[0][p] = make_float2(wia[0][2*p], wia[0][2*p+1]);
      wip[1][p] = make_float2(wia[1][2*p], wia[1][2*p+1]);
      wip[2][p] = make_float2(wia[2][2*p], wia[2][2*p+1]);
      wip[3][p] = make_float2(wia[3][2*p], wia[3][2*p+1]);
      n0p[p]  = make_float2(nn0[2*p], nn0[2*p+1]);
      n1p[p]  = make_float2(nn1[2*p], nn1[2*p+1]);
      ma0p[p] = make_float2(mm0[2*p], mm0[2*p+1]);
      ma1p[p] = make_float2(mm1[2*p], mm1[2*p+1]);
      wo0p[p] = make_float2(ww0[2*p], ww0[2*p+1]);
      wo1p[p] = make_float2(ww1[2*p], ww1[2*p+1]);
      hh[p]   = make_float2(h0v[2*p], h0v[2*p+1]);
    }
  }

  // ---- initial r and partial dot products ----
  float pz0, pz1, po0, po1;
  {
    float2 az0 = make_float2(0,0), az1 = az0, ao0 = az0, ao1 = az0;
    #pragma unroll
    for (int p = 0; p < PAIRS; p++) {
      float2 r2 = tanh2m(hh[p]);
      az0 = ffma2(r2, n0p[p], az0);
      az1 = ffma2(r2, n1p[p], az1);
      ao0 = ffma2(r2, wo0p[p], ao0);
      ao1 = ffma2(r2, wo1p[p], ao1);
    }
    pz0 = az0.x + az0.y; pz1 = az1.x + az1.y;
    po0 = ao0.x + ao0.y; po1 = ao1.x + ao1.y;
  }

  const float2 OMA2 = make_float2(OMA_F, OMA_F);
  const float2 SIG2 = make_float2(SIG_F, SIG_F);
  float* scr = g_scratch + (size_t)b * (TT * NWARPS * 2) + warp * 2;

  // ---- main scan ----
  for (int t = 0; t < TT; t++) {
    const int pb = t & 1;
    // stage-1: warp butterfly of [z0, z1, o_prev0, o_prev1]; all lanes get sums
    warp_sum4(pz0, pz1, po0, po1);
    if (lane == 0)      s_red[pb * 16 + warp]     = pz0;
    else if (lane == 1) s_red[pb * 16 + 8 + warp] = pz1;
    else if (lane == 2 && t > 0)
      *reinterpret_cast<float2*>(scr + (size_t)(t - 1) * (NWARPS * 2)) = make_float2(po0, po1);

    __syncthreads();

    // prefetch noise for t+3 (after barrier: all warps done reading that slot)
    int tp = t + 3; if (tp >= TT) tp = TT - 1;
    uint32_t soff = (uint32_t)(((t + 3) & 3) * HID * 4);
    cp16(sn_u32 + soff,      nbase + (size_t)tp * HID);
    cp16(sn_u32 + soff + 16, nbase + (size_t)tp * HID + 4);
    CP_COMMIT();

    // stage-2 (z only): 16 partials value-major, 3-level butterfly, broadcast
    float v = (lane < 16) ? s_red[pb * 16 + lane] : 0.f;
    v += __shfl_xor_sync(0xffffffffu, v, 4);
    v += __shfl_xor_sync(0xffffffffu, v, 2);
    v += __shfl_xor_sync(0xffffffffu, v, 1);
    const float z0 = __shfl_sync(0xffffffffu, v, 0);
    const float z1 = __shfl_sync(0xffffffffu, v, 8);

    CP_WAIT3();
    const float* np = s_noise + (t & 3) * HID + u0;
    float4 ga = *reinterpret_cast<const float4*>(np);
    float4 gb = *reinterpret_cast<const float4*>(np + 4);
    float4 xv = reinterpret_cast<const float4*>(s_in)[t];

    const float2 z0_2 = make_float2(z0, z0), z1_2 = make_float2(z1, z1);
    const float2 x0_2 = make_float2(xv.x, xv.x), x1_2 = make_float2(xv.y, xv.y);
    const float2 x2_2 = make_float2(xv.z, xv.z), x3_2 = make_float2(xv.w, xv.w);
    float2 gg[PAIRS] = { make_float2(ga.x, ga.y), make_float2(ga.z, ga.w),
                         make_float2(gb.x, gb.y), make_float2(gb.z, gb.w) };

    float2 az0 = make_float2(0,0), az1 = az0, ao0 = az0, ao1 = az0;
    #pragma unroll
    for (int p = 0; p < PAIRS; p++) {
      // h = 0.8h + 0.05*noise + alpha*(m z) + alpha*(wi x)   [alpha pre-folded]
      float2 acc = fmul2(z0_2, ma0p[p]);
      acc = ffma2(z1_2, ma1p[p], acc);
      acc = ffma2(OMA2, hh[p], acc);
      acc = ffma2(SIG2, gg[p], acc);
      acc = ffma2(x0_2, wip[0][p], acc);
      acc = ffma2(x1_2, wip[1][p], acc);
      acc = ffma2(x2_2, wip[2][p], acc);
      acc = ffma2(x3_2, wip[3][p], acc);
      hh[p] = acc;
      float2 r2 = tanh2m(acc);
      az0 = ffma2(r2, n0p[p], az0);
      az1 = ffma2(r2, n1p[p], az1);
      ao0 = ffma2(r2, wo0p[p], ao0);
      ao1 = ffma2(r2, wo1p[p], ao1);
    }
    pz0 = az0.x + az0.y; pz1 = az1.x + az1.y;
    po0 = ao0.x + ao0.y; po1 = ao1.x + ao1.y;
  }

  // ---- final per-warp output partial (r of step T-1) ----
  {
    float d0 = 0.f, d1 = 0.f;
    warp_sum4(po0, po1, d0, d1);
    if (lane == 2)
      *reinterpret_cast<float2*>(scr + (size_t)(TT - 1) * (NWARPS * 2)) = make_float2(po0, po1);
  }
}

// pass 2: out[b,t,:] = sum over 8 warps of g_scratch[b,t,w,:]
__global__ void out_reduce(float* __restrict__ out)
{
  int i = blockIdx.x * 256 + threadIdx.x;   // i over 32*1000 (b,t) pairs
  if (i >= 32 * TT) return;
  const float4* p = reinterpret_cast<const float4*>(g_scratch + (size_t)i * (NWARPS * 2));
  float4 a = p[0], c = p[1], d = p[2], e = p[3];
  float o0 = (a.x + a.z) + (c.x + c.z) + (d.x + d.z) + (e.x + e.z);
  float o1 = (a.y + a.w) + (c.y + c.w) + (d.y + d.w) + (e.y + e.w);
  reinterpret_cast<float2*>(out)[i] = make_float2(o0, o1);
}

extern "C" void kernel_launch(void* const* d_in, const int* in_sizes, int n_in,
                              void* d_out, int out_size) {
  const float* input = (const float*)d_in[0];
  const float* noise = (const float*)d_in[1];
  const float* wi_w  = (const float*)d_in[2];
  const float* m_w   = (const float*)d_in[3];
  const float* n_w   = (const float*)d_in[4];
  const float* wo_w  = (const float*)d_in[5];
  const float* wi_b  = (const float*)d_in[6];
  const float* m_b   = (const float*)d_in[7];
  const float* n_b   = (const float*)d_in[8];
  const float* h0_w  = (const float*)d_in[9];
  const float* basis = (const float*)d_in[10];
  const float* sup   = (const float*)d_in[11];
  float* out = (float*)d_out;

  cudaFuncSetAttribute(rnn_main, cudaFuncAttributeMaxDynamicSharedMemorySize, SMEM_BYTES);
  rnn_main<<<32, NTHREADS, SMEM_BYTES>>>(input, noise, wi_w, m_w, n_w, wo_w,
                                         wi_b, m_b, n_b, h0_w, basis, sup);
  out_reduce<<<(32 * TT + 255) / 256, 256>>>(out);
}

// round 7
// speedup vs baseline: 1.5239x; 1.4818x over previous
#include <cuda_runtime.h>
#include <cstdint>

// SupportLowRankRNN: B=32, T=1000, H=2048, I=4, R=2, O=2, S=2, G=8
#define TT       1000
#define HID      2048
#define NTHREADS 256
#define NWARPS   8
#define UNITS    8          // hidden units per thread
#define PAIRS    4          // float2 pairs per thread
#define NSLOT    8          // noise ring slots
#define PFD      4          // prefetch distance
#define ALPHA_F  0.2f
#define OMA_F    0.8f
#define SIG_F    0.05f
#define L2E2X    2.8853900817779268f  // 2*log2(e)

// smem layout (floats)
#define SM_NOISE 0                         // 8 slots * 2048 = 16384
#define SM_IN    (NSLOT*HID)               // 4000 (input seq 1000*4)
#define SM_RED   (SM_IN + 4000)            // 2*8 float2 = 32 floats (parity-buffered z partials)
#define SM_W     (SM_RED + 32)             // 192 staged weights
#define SM_FLOATS (SM_W + 192)
#define SMEM_BYTES (SM_FLOATS * 4)         // ~82.4 KB

// weight staging offsets inside SM_W
#define W_WI  0
#define W_M   64
#define W_N   96
#define W_WO  128
#define W_WIB 160
#define W_MB  168
#define W_NB  172
#define W_H0  176

// per-thread output partials: [b][t][tid][2]  (65.5 MB)
__device__ float g_scratch[(size_t)32 * TT * NTHREADS * 2];

__device__ __forceinline__ unsigned long long f2u(float2 v){ union{float2 f; unsigned long long u;} x; x.f=v; return x.u; }
__device__ __forceinline__ float2 u2f(unsigned long long u){ union{float2 f; unsigned long long u;} x; x.u=u; return x.f; }
__device__ __forceinline__ float2 ffma2(float2 a,float2 b,float2 c){
  unsigned long long D; asm("fma.rn.f32x2 %0,%1,%2,%3;":"=l"(D):"l"(f2u(a)),"l"(f2u(b)),"l"(f2u(c))); return u2f(D);
}
__device__ __forceinline__ float2 fmul2(float2 a,float2 b){
  unsigned long long D; asm("mul.rn.f32x2 %0,%1,%2;":"=l"(D):"l"(f2u(a)),"l"(f2u(b))); return u2f(D);
}
__device__ __forceinline__ float2 fadd2(float2 a,float2 b){
  unsigned long long D; asm("add.rn.f32x2 %0,%1,%2;":"=l"(D):"l"(f2u(a)),"l"(f2u(b))); return u2f(D);
}
__device__ __forceinline__ float ex2a(float x){ float y; asm("ex2.approx.f32 %0,%1;":"=f"(y):"f"(x)); return y; }
__device__ __forceinline__ float rcpa(float x){ float y; asm("rcp.approx.f32 %0,%1;":"=f"(y):"f"(x)); return y; }
__device__ __forceinline__ void cp16(uint32_t s, const void* g){
  asm volatile("cp.async.ca.shared.global [%0], [%1], 16;"::"r"(s),"l"(g));
}
#define CP_COMMIT() asm volatile("cp.async.commit_group;")
#define CP_WAIT3()  asm volatile("cp.async.wait_group 3;")

// 5-level butterfly on 2 independent values (z only)
__device__ __forceinline__ void warp_sum2(float& a, float& b){
  #pragma unroll
  for (int o = 16; o > 0; o >>= 1) {
    a += __shfl_xor_sync(0xffffffffu, a, o);
    b += __shfl_xor_sync(0xffffffffu, b, o);
  }
}

// tanh pair with ONE rcp (batched reciprocal); upper clamp only
// (ex2(-big)=0 is exact: result -> -1 with no NaN path)
__device__ __forceinline__ float2 tanh2m(float2 h){
  float2 ea = fmul2(h, make_float2(L2E2X, L2E2X));
  float a0 = fminf(ea.x, 60.f);
  float a1 = fminf(ea.y, 60.f);
  float2 d = fadd2(make_float2(ex2a(a0), ex2a(a1)), make_float2(1.f, 1.f));
  float inv = rcpa(d.x * d.y);
  float s = -2.f * inv;
  return make_float2(fmaf(s, d.y, 1.f), fmaf(s, d.x, 1.f));
}

__global__ void __launch_bounds__(NTHREADS, 1)
rnn_main(const float* __restrict__ input,   // (32,1000,4)
         const float* __restrict__ noise,   // (32,1000,2048)
         const float* __restrict__ wi_w, const float* __restrict__ m_w,
         const float* __restrict__ n_w, const float* __restrict__ wo_w,
         const float* __restrict__ wi_b, const float* __restrict__ m_b,
         const float* __restrict__ n_b, const float* __restrict__ h0_w,
         const float* __restrict__ basis,   // (8,2048)
         const float* __restrict__ sup)     // (2,2048)
{
  const int b    = blockIdx.x;
  const int tid  = threadIdx.x;
  const int lane = tid & 31;
  const int warp = tid >> 5;
  const int u0   = tid * UNITS;

  extern __shared__ __align__(16) float sm[];
  float* s_noise = sm + SM_NOISE;
  float* s_in    = sm + SM_IN;
  float4* s_red4 = reinterpret_cast<float4*>(sm + SM_RED);   // [parity][4] float4 = 8 float2
  float2* s_red2 = reinterpret_cast<float2*>(sm + SM_RED);
  float* s_w     = sm + SM_W;

  // ---- stage tiny weights to smem ----
  if (tid < 64)        s_w[tid] = wi_w[tid];
  else if (tid < 96)   s_w[tid] = m_w[tid - 64];
  else if (tid < 128)  s_w[tid] = n_w[tid - 96];
  else if (tid < 160)  s_w[tid] = wo_w[tid - 128];
  else if (tid < 168)  s_w[tid] = wi_b[tid - 160];
  else if (tid < 172)  s_w[tid] = m_b[tid - 168];
  else if (tid < 176)  s_w[tid] = n_b[tid - 172];
  else if (tid < 192)  s_w[tid] = h0_w[tid - 176];

  // ---- preload full input sequence (16KB) ----
  const float4* inb = reinterpret_cast<const float4*>(input + (size_t)b * (TT * 4));
  for (int i = tid; i < TT; i += NTHREADS)
    reinterpret_cast<float4*>(s_in)[i] = inb[i];

  // ---- noise cp.async prologue: slots 0..3 (distance-4 pipeline) ----
  const float* nbase = noise + (size_t)b * TT * HID + u0;
  uint32_t sn_u32 = (uint32_t)__cvta_generic_to_shared(s_noise + u0);
  #pragma unroll
  for (int ps = 0; ps < PFD; ps++) {
    cp16(sn_u32 + (uint32_t)ps * HID * 4,      nbase + (size_t)ps * HID);
    cp16(sn_u32 + (uint32_t)ps * HID * 4 + 16, nbase + (size_t)ps * HID + 4);
    CP_COMMIT();
  }

  __syncthreads();  // s_w + s_in ready

  // ---- per-unit params; packed float2 pairs ----
  float2 wip[4][PAIRS], n0p[PAIRS], n1p[PAIRS], ma0p[PAIRS], ma1p[PAIRS],
         wo0p[PAIRS], wo1p[PAIRS], hh[PAIRS];
  {
    float wia[4][UNITS], nn0[UNITS], nn1[UNITS], mm0[UNITS], mm1[UNITS],
          ww0[UNITS], ww1[UNITS], h0v[UNITS];
    #pragma unroll
    for (int j = 0; j < UNITS; j++) {
      const int h = u0 + j;
      float B[8];
      #pragma unroll
      for (int g = 0; g < 8; g++) B[g] = basis[g * HID + h];
      const float su0 = sup[h], su1 = sup[HID + h];
      #pragma unroll
      for (int x = 0; x < 4; x++) {
        float t0 = s_w[W_WIB + x*2 + 0], t1 = s_w[W_WIB + x*2 + 1];
        #pragma unroll
        for (int g = 0; g < 8; g++) { t0 += s_w[W_WI + x*16 + g]*B[g]; t1 += s_w[W_WI + x*16 + 8 + g]*B[g]; }
        wia[x][j] = ALPHA_F * (t0*su0 + t1*su1);
      }
      #pragma unroll
      for (int r = 0; r < 2; r++) {
        float tm0 = s_w[W_MB + r*2 + 0], tm1 = s_w[W_MB + r*2 + 1];
        float tn0 = s_w[W_NB + r*2 + 0], tn1 = s_w[W_NB + r*2 + 1];
        #pragma unroll
        for (int g = 0; g < 8; g++) {
          tm0 += s_w[W_M + r*16 + g]*B[g];  tm1 += s_w[W_M + r*16 + 8 + g]*B[g];
          tn0 += s_w[W_N + r*16 + g]*B[g];  tn1 += s_w[W_N + r*16 + 8 + g]*B[g];
        }
        float mv = ALPHA_F * (tm0*su0 + tm1*su1);
        float nv = tn0*su0 + tn1*su1;
        if (r == 0) { mm0[j] = mv; nn0[j] = nv; } else { mm1[j] = mv; nn1[j] = nv; }
      }
      #pragma unroll
      for (int o = 0; o < 2; o++) {
        float t0 = 0.f, t1 = 0.f;
        #pragma unroll
        for (int g = 0; g < 8; g++) { t0 += s_w[W_WO + o*16 + g]*B[g]; t1 += s_w[W_WO + o*16 + 8 + g]*B[g]; }
        float wv = t0*su0 + t1*su1;
        if (o == 0) ww0[j] = wv; else ww1[j] = wv;
      }
      {
        float t0 = 0.f, t1 = 0.f;
        #pragma unroll
        for (int g = 0; g < 8; g++) { t0 += s_w[W_H0 + g]*B[g]; t1 += s_w[W_H0 + 8 + g]*B[g]; }
        h0v[j] = t0*su0 + t1*su1;
      }
    }
    #pragma unroll
    for (int p = 0; p < PAIRS; p++) {
      wip[0][p] = make_float2(wia[0][2*p], wia[0][2*p+1]);
      wip[1][p] = make_float2(wia[1][2*p], wia[1][2*p+1]);
      wip[2][p] = make_float2(wia[2][2*p], wia[2][2*p+1]);
      wip[3][p] = make_float2(wia[3][2*p], wia[3][2*p+1]);
      n0p[p]  = make_float2(nn0[2*p], nn0[2*p+1]);
      n1p[p]  = make_float2(nn1[2*p], nn1[2*p+1]);
      ma0p[p] = make_float2(mm0[2*p], mm0[2*p+1]);
      ma1p[p] = make_float2(mm1[2*p], mm1[2*p+1]);
      wo0p[p] = make_float2(ww0[2*p], ww0[2*p+1]);
      wo1p[p] = make_float2(ww1[2*p], ww1[2*p+1]);
      hh[p]   = make_float2(h0v[2*p], h0v[2*p+1]);
    }
  }

  // ---- initial pz from r_init = tanh(h0) ----
  float pz0, pz1;
  {
    float2 az0 = make_float2(0,0), az1 = az0;
    #pragma unroll
    for (int p = 0; p < PAIRS; p++) {
      float2 r2 = tanh2m(hh[p]);
      az0 = ffma2(r2, n0p[p], az0);
      az1 = ffma2(r2, n1p[p], az1);
    }
    pz0 = az0.x + az0.y; pz1 = az1.x + az1.y;
  }

  const float2 OMA2 = make_float2(OMA_F, OMA_F);
  const float2 SIG2 = make_float2(SIG_F, SIG_F);
  float2* scr = reinterpret_cast<float2*>(g_scratch) + (size_t)b * (TT * NTHREADS) + tid;

  // ---- main scan ----
  for (int t = 0; t < TT; t++) {
    const int pb = t & 1;
    // z-butterfly over warp; all lanes get warp sums
    warp_sum2(pz0, pz1);
    if (lane == 0) s_red2[pb * 8 + warp] = make_float2(pz0, pz1);

    // ensure noise slot t complete (3 newer groups allowed: t+1..t+3)
    CP_WAIT3();
    const float* np = s_noise + (t & (NSLOT-1)) * HID + u0;
    float4 ga = *reinterpret_cast<const float4*>(np);
    float4 gb = *reinterpret_cast<const float4*>(np + 4);
    float4 xv = reinterpret_cast<const float4*>(s_in)[t];

    // z-independent precompute (off the critical chain)
    const float2 x0_2 = make_float2(xv.x, xv.x), x1_2 = make_float2(xv.y, xv.y);
    const float2 x2_2 = make_float2(xv.z, xv.z), x3_2 = make_float2(xv.w, xv.w);
    float2 gg[PAIRS] = { make_float2(ga.x, ga.y), make_float2(ga.z, ga.w),
                         make_float2(gb.x, gb.y), make_float2(gb.z, gb.w) };
    float2 pre[PAIRS];
    #pragma unroll
    for (int p = 0; p < PAIRS; p++) {
      float2 a = fmul2(SIG2, gg[p]);
      a = ffma2(OMA2, hh[p], a);
      a = ffma2(x0_2, wip[0][p], a);
      a = ffma2(x1_2, wip[1][p], a);
      a = ffma2(x2_2, wip[2][p], a);
      a = ffma2(x3_2, wip[3][p], a);
      pre[p] = a;
    }

    __syncthreads();

    // prefetch noise slot t+4 (safe: all reads of this slot ended before bar(t-3))
    int tp = t + PFD; if (tp >= TT) tp = TT - 1;
    uint32_t soff = (uint32_t)(((t + PFD) & (NSLOT-1)) * HID * 4);
    cp16(sn_u32 + soff,      nbase + (size_t)tp * HID);
    cp16(sn_u32 + soff + 16, nbase + (size_t)tp * HID + 4);
    CP_COMMIT();

    // stage-2: broadcast LDS of ALL 8 warp partials (4 x float4) + fadd2 tree
    float4 q0 = s_red4[pb*4 + 0], q1 = s_red4[pb*4 + 1];
    float4 q2 = s_red4[pb*4 + 2], q3 = s_red4[pb*4 + 3];
    float2 sA = fadd2(make_float2(q0.x, q0.y), make_float2(q0.z, q0.w));
    float2 sB = fadd2(make_float2(q1.x, q1.y), make_float2(q1.z, q1.w));
    float2 sC = fadd2(make_float2(q2.x, q2.y), make_float2(q2.z, q2.w));
    float2 sD = fadd2(make_float2(q3.x, q3.y), make_float2(q3.z, q3.w));
    float2 zz = fadd2(fadd2(sA, sB), fadd2(sC, sD));
    const float2 z0_2 = make_float2(zz.x, zz.x), z1_2 = make_float2(zz.y, zz.y);

    float2 az0 = make_float2(0,0), az1 = az0, ao0 = az0, ao1 = az0;
    #pragma unroll
    for (int p = 0; p < PAIRS; p++) {
      float2 tzz = ffma2(z1_2, ma1p[p], pre[p]);
      float2 acc = ffma2(z0_2, ma0p[p], tzz);
      hh[p] = acc;
      float2 r2 = tanh2m(acc);
      az0 = ffma2(r2, n0p[p], az0);
      az1 = ffma2(r2, n1p[p], az1);
      ao0 = ffma2(r2, wo0p[p], ao0);
      ao1 = ffma2(r2, wo1p[p], ao1);
    }
    pz0 = az0.x + az0.y; pz1 = az1.x + az1.y;
    // per-thread output partial straight to scratch (no in-loop reduction)
    scr[(size_t)t * NTHREADS] = make_float2(ao0.x + ao0.y, ao1.x + ao1.y);
  }
}

// pass 2: out[b,t,:] = sum over 256 threads of per-thread partials.
// one warp per (b,t): each lane sums 8 float2 (4 global float4 loads), then butterfly.
__global__ void __launch_bounds__(256, 8)
out_reduce(float* __restrict__ out)
{
  const int warp = threadIdx.x >> 5;
  const int lane = threadIdx.x & 31;
  const int i = blockIdx.x * 8 + warp;           // (b,t) pair, 32*1000 total
  if (i >= 32 * TT) return;
  const float4* p = reinterpret_cast<const float4*>(g_scratch + (size_t)i * (NTHREADS * 2)) + lane * 4;
  float4 a = p[0], c = p[1], d = p[2], e = p[3];
  float o0 = (a.x + a.z) + (c.x + c.z) + (d.x + d.z) + (e.x + e.z);
  float o1 = (a.y + a.w) + (c.y + c.w) + (d.y + d.w) + (e.y + e.w);
  #pragma unroll
  for (int o = 16; o > 0; o >>= 1) {
    o0 += __shfl_xor_sync(0xffffffffu, o0, o);
    o1 += __shfl_xor_sync(0xffffffffu, o1, o);
  }
  if (lane == 0)
    reinterpret_cast<float2*>(out)[i] = make_float2(o0, o1);
}

extern "C" void kernel_launch(void* const* d_in, const int* in_sizes, int n_in,
                              void* d_out, int out_size) {
  const float* input = (const float*)d_in[0];
  const float* noise = (const float*)d_in[1];
  const float* wi_w  = (const float*)d_in[2];
  const float* m_w   = (const float*)d_in[3];
  const float* n_w   = (const float*)d_in[4];
  const float* wo_w  = (const float*)d_in[5];
  const float* wi_b  = (const float*)d_in[6];
  const float* m_b   = (const float*)d_in[7];
  const float* n_b   = (const float*)d_in[8];
  const float* h0_w  = (const float*)d_in[9];
  const float* basis = (const float*)d_in[10];
  const float* sup   = (const float*)d_in[11];
  float* out = (float*)d_out;

  cudaFuncSetAttribute(rnn_main, cudaFuncAttributeMaxDynamicSharedMemorySize, SMEM_BYTES);
  rnn_main<<<32, NTHREADS, SMEM_BYTES>>>(input, noise, wi_w, m_w, n_w, wo_w,
                                         wi_b, m_b, n_b, h0_w, basis, sup);
  out_reduce<<<(32 * TT + 7) / 8, 256>>>(out);
}